// round 2
// baseline (speedup 1.0000x reference)
#include <cuda_runtime.h>
#include <cuda_bf16.h>
#include <math.h>

#define MAXN 50000
#define MAXE 800000

// ---------------- device scratch (static allocation, allowed) ----------------
__device__ __align__(16) float g_qkvs[(size_t)MAXN * 512]; // per node: q[128]|k[128]|v[128]|skip[128]
__device__ __align__(16) float g_agg [(size_t)MAXN * 128]; // attention out + skip (concat heads)
__device__ float  g_alpha[(size_t)MAXE * 2];               // exp(logit) per edge per head (CSR order)
__device__ int    g_esrc [MAXE];
__device__ int    g_edst [MAXE];
__device__ int    g_src  [MAXE];                            // src node per CSR slot
__device__ int    g_cnt  [MAXN];
__device__ int    g_cur  [MAXN];
__device__ int    g_rowptr[MAXN + 1];
__device__ int    g_blksum[64];
__device__ int    g_is64;
__device__ double g_stats[2];                               // sum, sumsq

// ---------------- edge dtype sniffing + conversion ----------------
// If edge_index is int64 (LE, values in [0,50000)), every odd 32-bit word is 0.
// For genuine int32 data, 32 consecutive odd words all-zero has probability ~0.
__global__ void k_detect(const void* __restrict__ ei) {
    if (threadIdx.x == 0 && blockIdx.x == 0) {
        const int* w = (const int*)ei;
        int all0 = 1;
        for (int i = 1; i < 64; i += 2) all0 &= (w[i] == 0);
        g_is64 = all0;
    }
}

__global__ void k_convert(const void* __restrict__ ei, int e) {
    int i = blockIdx.x * blockDim.x + threadIdx.x;
    if (i >= 2 * e) return;
    int v;
    if (g_is64) v = (int)((const long long*)ei)[i];
    else        v = ((const int*)ei)[i];
    if (i < e) g_esrc[i] = v;
    else       g_edst[i - e] = v;
}

// ---------------- init ----------------
__global__ void k_init(int n) {
    int i = blockIdx.x * blockDim.x + threadIdx.x;
    if (i < n) { g_cnt[i] = 0; g_cur[i] = 0; }
    if (i == 0) { g_stats[0] = 0.0; g_stats[1] = 0.0; }
}

// ---------------- fused QKV+skip projection: [n,64] @ [64,128] x4 ----------------
// grid: (ceil(n/64), 4). block 256. BM=64, BN=128, K in 2 chunks of 32.
__global__ void k_gemm(const float* __restrict__ x,
                       const float* __restrict__ Wq, const float* __restrict__ bq,
                       const float* __restrict__ Wk, const float* __restrict__ bk,
                       const float* __restrict__ Wv, const float* __restrict__ bv,
                       const float* __restrict__ Wsk, const float* __restrict__ bsk,
                       int n) {
    __shared__ float Xs[64 * 32];
    __shared__ float Wsh[32 * 128];
    int m = blockIdx.y;
    const float* W    = (m == 0) ? Wq : (m == 1) ? Wk : (m == 2) ? Wv : Wsk;
    const float* bias = (m == 0) ? bq : (m == 1) ? bk : (m == 2) ? bv : bsk;

    int tx = threadIdx.x & 15;   // col group
    int ty = threadIdx.x >> 4;   // row group
    int row0 = blockIdx.x * 64;

    float acc[4][8];
#pragma unroll
    for (int i = 0; i < 4; i++)
#pragma unroll
        for (int j = 0; j < 8; j++) acc[i][j] = 0.f;

    for (int kc = 0; kc < 2; kc++) {
        // load X tile: 64 rows x 32 k  (512 float4)
        for (int t = threadIdx.x; t < 512; t += 256) {
            int r = t >> 3, q = t & 7;
            float4 xv = make_float4(0.f, 0.f, 0.f, 0.f);
            if (row0 + r < n) xv = ((const float4*)x)[(size_t)(row0 + r) * 16 + kc * 8 + q];
            ((float4*)Xs)[r * 8 + q] = xv;
        }
        // load W tile: 32 k x 128 cols (1024 float4)
        for (int t = threadIdx.x; t < 1024; t += 256) {
            ((float4*)Wsh)[t] = ((const float4*)W)[kc * 1024 + t];
        }
        __syncthreads();
#pragma unroll
        for (int k = 0; k < 32; k++) {
            float xf[4], wf[8];
#pragma unroll
            for (int i = 0; i < 4; i++) xf[i] = Xs[(ty + i * 16) * 32 + k];
#pragma unroll
            for (int j = 0; j < 8; j++) wf[j] = Wsh[k * 128 + tx + j * 16];
#pragma unroll
            for (int i = 0; i < 4; i++)
#pragma unroll
                for (int j = 0; j < 8; j++) acc[i][j] = fmaf(xf[i], wf[j], acc[i][j]);
        }
        __syncthreads();
    }
#pragma unroll
    for (int i = 0; i < 4; i++) {
        int r = row0 + ty + i * 16;
        if (r < n) {
#pragma unroll
            for (int j = 0; j < 8; j++) {
                int c = tx + j * 16;
                g_qkvs[(size_t)r * 512 + m * 128 + c] = acc[i][j] + __ldg(&bias[c]);
            }
        }
    }
}

// ---------------- CSR build ----------------
__global__ void k_hist(int e) {
    int i = blockIdx.x * blockDim.x + threadIdx.x;
    if (i < e) atomicAdd(&g_cnt[g_edst[i]], 1);
}

__global__ void k_scan1(int n) {
    __shared__ int sh[1024];
    int tid = threadIdx.x;
    int i = blockIdx.x * 1024 + tid;
    int v = (i < n) ? g_cnt[i] : 0;
    sh[tid] = v;
    __syncthreads();
    for (int off = 1; off < 1024; off <<= 1) {
        int t = (tid >= off) ? sh[tid - off] : 0;
        __syncthreads();
        sh[tid] += t;
        __syncthreads();
    }
    if (i < n) g_rowptr[i] = sh[tid] - v;       // exclusive within block
    if (tid == 1023) g_blksum[blockIdx.x] = sh[1023];
}

__global__ void k_scan2(int nb, int n) {
    if (threadIdx.x == 0 && blockIdx.x == 0) {
        int acc = 0;
        for (int b = 0; b < nb; b++) { int t = g_blksum[b]; g_blksum[b] = acc; acc += t; }
        g_rowptr[n] = acc;
    }
}

__global__ void k_scan3(int n) {
    int i = blockIdx.x * 1024 + threadIdx.x;
    if (i < n) g_rowptr[i] += g_blksum[blockIdx.x];
}

__global__ void k_scatter(int e) {
    int i = blockIdx.x * blockDim.x + threadIdx.x;
    if (i < e) {
        int src = g_esrc[i];
        int dst = g_edst[i];
        int pos = g_rowptr[dst] + atomicAdd(&g_cur[dst], 1);
        g_src[pos] = src;
    }
}

// ---------------- attention: one warp per dst node ----------------
// lane l holds float4 slot l of the 128-float (2-head) vectors.
// lanes 0..15 = head 0, lanes 16..31 = head 1.
__global__ void k_attn(int n) {
    int node = blockIdx.x * 8 + (threadIdx.x >> 5);
    if (node >= n) return;
    int lane = threadIdx.x & 31;
    int h = lane >> 4;
    const float4* base = (const float4*)g_qkvs;

    float4 q4 = base[(size_t)node * 128 + lane];
    int beg = g_rowptr[node], end = g_rowptr[node + 1];

    float denom = 0.f;
    for (int t = beg; t < end; t++) {
        int src = g_src[t];
        float4 k4 = base[(size_t)src * 128 + 32 + lane];
        float p = q4.x * k4.x + q4.y * k4.y + q4.z * k4.z + q4.w * k4.w;
        p += __shfl_xor_sync(0xffffffffu, p, 8);
        p += __shfl_xor_sync(0xffffffffu, p, 4);
        p += __shfl_xor_sync(0xffffffffu, p, 2);
        p += __shfl_xor_sync(0xffffffffu, p, 1);
        // logits are tiny (|alpha| < ~2): exp without max-subtraction is exact-equivalent
        float w = __expf(p * 0.125f);
        denom += w;
        if ((lane & 15) == 0) g_alpha[(size_t)t * 2 + h] = w;
    }
    __syncwarp();
    float inv = 1.f / (denom + 1e-16f);

    float4 acc = base[(size_t)node * 128 + 96 + lane];   // skip connection
    for (int t = beg; t < end; t++) {
        int src = g_src[t];
        float4 v4 = base[(size_t)src * 128 + 64 + lane];
        float a = g_alpha[(size_t)t * 2 + h] * inv;
        acc.x = fmaf(a, v4.x, acc.x);
        acc.y = fmaf(a, v4.y, acc.y);
        acc.z = fmaf(a, v4.z, acc.z);
        acc.w = fmaf(a, v4.w, acc.w);
    }
    ((float4*)g_agg)[(size_t)node * 32 + lane] = acc;
}

// ---------------- final GEMM [n,128]@[128,64] + bc, fused LN stats ----------------
// grid ceil(n/64), block 256. BM=64, BN=64, K in 4 chunks of 32.
__global__ void k_final(const float* __restrict__ Wc, const float* __restrict__ bc,
                        float* __restrict__ out, int n) {
    __shared__ float Ash[64 * 32];
    __shared__ float Wch[32 * 64];
    __shared__ float rs[8], rss[8];

    int tx = threadIdx.x & 15;
    int ty = threadIdx.x >> 4;
    int row0 = blockIdx.x * 64;

    float acc[4][4];
#pragma unroll
    for (int i = 0; i < 4; i++)
#pragma unroll
        for (int j = 0; j < 4; j++) acc[i][j] = 0.f;

    for (int kc = 0; kc < 4; kc++) {
        for (int t = threadIdx.x; t < 512; t += 256) {        // 64 rows x 32 k
            int r = t >> 3, q = t & 7;
            float4 av = make_float4(0.f, 0.f, 0.f, 0.f);
            if (row0 + r < n) av = ((const float4*)g_agg)[(size_t)(row0 + r) * 32 + kc * 8 + q];
            ((float4*)Ash)[r * 8 + q] = av;
        }
        for (int t = threadIdx.x; t < 512; t += 256) {        // 32 k x 64 cols
            int k = t >> 4, c4 = t & 15;
            ((float4*)Wch)[k * 16 + c4] = ((const float4*)Wc)[(kc * 32 + k) * 16 + c4];
        }
        __syncthreads();
#pragma unroll
        for (int k = 0; k < 32; k++) {
            float xf[4], wf[4];
#pragma unroll
            for (int i = 0; i < 4; i++) xf[i] = Ash[(ty + i * 16) * 32 + k];
#pragma unroll
            for (int j = 0; j < 4; j++) wf[j] = Wch[k * 64 + tx + j * 16];
#pragma unroll
            for (int i = 0; i < 4; i++)
#pragma unroll
                for (int j = 0; j < 4; j++) acc[i][j] = fmaf(xf[i], wf[j], acc[i][j]);
        }
        __syncthreads();
    }

    float s = 0.f, ss = 0.f;
#pragma unroll
    for (int i = 0; i < 4; i++) {
        int r = row0 + ty + i * 16;
        if (r < n) {
#pragma unroll
            for (int j = 0; j < 4; j++) {
                int c = tx + j * 16;
                float v = acc[i][j] + __ldg(&bc[c]);
                out[(size_t)r * 64 + c] = v;
                s += v;
                ss += v * v;
            }
        }
    }
    // reduce LN stats
#pragma unroll
    for (int off = 16; off > 0; off >>= 1) {
        s  += __shfl_xor_sync(0xffffffffu, s, off);
        ss += __shfl_xor_sync(0xffffffffu, ss, off);
    }
    int wid = threadIdx.x >> 5, lane = threadIdx.x & 31;
    if (lane == 0) { rs[wid] = s; rss[wid] = ss; }
    __syncthreads();
    if (threadIdx.x == 0) {
        double S = 0.0, SS = 0.0;
        for (int w = 0; w < 8; w++) { S += (double)rs[w]; SS += (double)rss[w]; }
        atomicAdd(&g_stats[0], S);
        atomicAdd(&g_stats[1], SS);
    }
}

// ---------------- graph-level LayerNorm ----------------
__global__ void k_norm(float* __restrict__ out, const float* __restrict__ gamma,
                       const float* __restrict__ beta, int total) {
    int i = blockIdx.x * blockDim.x + threadIdx.x;
    if (i < total) {
        double M = (double)total;
        double mean = g_stats[0] / M;
        double var  = g_stats[1] / M - mean * mean;
        if (var < 0.0) var = 0.0;
        float stdv = (float)sqrt(var);
        float v = out[i];
        int d = i & 63;
        out[i] = (v - (float)mean) / (stdv + 1e-5f) * __ldg(&gamma[d]) + __ldg(&beta[d]);
    }
}

// ---------------- launch ----------------
extern "C" void kernel_launch(void* const* d_in, const int* in_sizes, int n_in,
                              void* d_out, int out_size) {
    const float* x    = (const float*)d_in[0];
    const void*  ei   = d_in[1];
    const float* Wq   = (const float*)d_in[2];
    const float* bq   = (const float*)d_in[3];
    const float* Wk   = (const float*)d_in[4];
    const float* bk   = (const float*)d_in[5];
    const float* Wv   = (const float*)d_in[6];
    const float* bv   = (const float*)d_in[7];
    const float* Wsk  = (const float*)d_in[8];
    const float* bsk  = (const float*)d_in[9];
    const float* Wc   = (const float*)d_in[10];
    const float* bc   = (const float*)d_in[11];
    const float* gam  = (const float*)d_in[12];
    const float* bet  = (const float*)d_in[13];
    float* out = (float*)d_out;

    int n = in_sizes[0] / 64;
    int e = in_sizes[1] / 2;

    k_detect<<<1, 32>>>(ei);
    k_convert<<<(2 * e + 255) / 256, 256>>>(ei, e);
    k_init<<<(n + 255) / 256, 256>>>(n);
    k_gemm<<<dim3((n + 63) / 64, 4), 256>>>(x, Wq, bq, Wk, bk, Wv, bv, Wsk, bsk, n);
    k_hist<<<(e + 255) / 256, 256>>>(e);
    int nb = (n + 1023) / 1024;
    k_scan1<<<nb, 1024>>>(n);
    k_scan2<<<1, 32>>>(nb, n);
    k_scan3<<<nb, 1024>>>(n);
    k_scatter<<<(e + 255) / 256, 256>>>(e);
    k_attn<<<(n + 7) / 8, 256>>>(n);
    k_final<<<(n + 63) / 64, 256>>>(Wc, bc, out, n);
    k_norm<<<(n * 64 + 255) / 256, 256>>>(out, gam, bet, n * 64);
}